// round 15
// baseline (speedup 1.0000x reference)
#include <cuda_runtime.h>
#include <math.h>

#define NB   32
#define HID  64
#define LHW  64
#define LPIX (LHW*LHW)       // 4096
#define OHW  256
#define NPIX (OHW*OHW)       // 65536

#define OFF_HEAT  0
#define N_HEAT    (NB*NPIX)              // 2097152
#define OFF_COORD (N_HEAT)
#define OFF_LAB   (OFF_COORD + NB*10)    // 2097472
#define OFF_LOG   (OFF_LAB + NB*5)       // 2097632

// scratch (device globals: allocation-free)
__device__ __align__(16) float g_h1[NB*HID*LPIX];
__device__ __align__(16) float g_h2[NB*HID*LPIX];
__device__ __align__(16) float g_l64[NB*LPIX];
__device__ __align__(16) float g_rmax[NB*NPIX];

// ---------------------------------------------------------------------------
// f32x2 packed helpers (sm_103a FFMA2 path — per-lane IEEE fp32, bit-exact)
// ---------------------------------------------------------------------------
__device__ __forceinline__ unsigned long long pk2(float lo, float hi) {
    unsigned long long r;
    asm("mov.b64 %0, {%1, %2};" : "=l"(r) : "f"(lo), "f"(hi));
    return r;
}
__device__ __forceinline__ unsigned long long fma2(unsigned long long a,
                                                   unsigned long long b,
                                                   unsigned long long c) {
    unsigned long long d;
    asm("fma.rn.f32x2 %0, %1, %2, %3;" : "=l"(d) : "l"(a), "l"(b), "l"(c));
    return d;
}
__device__ __forceinline__ unsigned long long add2(unsigned long long a,
                                                   unsigned long long b) {
    unsigned long long d;
    asm("add.rn.f32x2 %0, %1, %2;" : "=l"(d) : "l"(a), "l"(b));
    return d;
}
__device__ __forceinline__ void unpk2(unsigned long long v, float &lo, float &hi) {
    asm("mov.b64 {%0, %1}, %2;" : "=f"(lo), "=f"(hi) : "l"(v));
}
__device__ __forceinline__ void cpasync16(unsigned dst, const void* src) {
    asm volatile("cp.async.ca.shared.global [%0], [%1], 16;"
                 :: "r"(dst), "l"(src) : "memory");
}
__device__ __forceinline__ void cpasync4(unsigned dst, const void* src) {
    asm volatile("cp.async.ca.shared.global [%0], [%1], 4;"
                 :: "r"(dst), "l"(src) : "memory");
}

// ---------------------------------------------------------------------------
// threefry2x32 (JAX-compatible, 20 rounds)
// ---------------------------------------------------------------------------
__device__ __forceinline__ void tf2x32(unsigned k0, unsigned k1,
                                       unsigned x0, unsigned x1,
                                       unsigned &o0, unsigned &o1)
{
    unsigned ks0 = k0, ks1 = k1, ks2 = k0 ^ k1 ^ 0x1BD11BDAu;
    x0 += ks0; x1 += ks1;
#define TFR(r) { x0 += x1; x1 = (x1 << (r)) | (x1 >> (32 - (r))); x1 ^= x0; }
    TFR(13) TFR(15) TFR(26) TFR(6)   x0 += ks1; x1 += ks2 + 1u;
    TFR(17) TFR(29) TFR(16) TFR(24)  x0 += ks2; x1 += ks0 + 2u;
    TFR(13) TFR(15) TFR(26) TFR(6)   x0 += ks0; x1 += ks1 + 3u;
    TFR(17) TFR(29) TFR(16) TFR(24)  x0 += ks1; x1 += ks2 + 4u;
    TFR(13) TFR(15) TFR(26) TFR(6)   x0 += ks2; x1 += ks0 + 5u;
#undef TFR
    o0 = x0; o1 = x1;
}

// ---------------------------------------------------------------------------
// dummy kernels: keep ncu's fixed profiling slot on conv3x3 (3 launches)
// ---------------------------------------------------------------------------
__global__ void dummy_k() {}

// ---------------------------------------------------------------------------
// conv3x3 (pad1) + inference BN + ReLU, f32x2-packed, cp.async double-buffered.
// Tile: full-width 64 x 16 rows, 16 oc per block; ICC=4 per chunk, 2 buffers.
// block 256 thr: tx=tid&31 -> x-pair 2tx; y0=(tid>>5)*2 -> rows y0, y0+1.
// grid (4 strips, NB, HID/16); 2 rows x 2 px x 16 oc per thread.
// smem rows stride 72: image col x at smem col x+4; cols 3 / 68 permanent 0.
// Weights in padded stride-12 layout -> consumed via LDS.128 x2 + LDS.32.
// ---------------------------------------------------------------------------
#define ICC 4
template<int CIN>
__global__ void __launch_bounds__(256, 2)
conv3x3_bn_relu(const float* __restrict__ x,  const float* __restrict__ w,
                const float* __restrict__ gg, const float* __restrict__ bb,
                const float* __restrict__ mm, const float* __restrict__ vv,
                float* __restrict__ out)
{
    __shared__ __align__(16) float s_in[2*ICC*18*72];    // 41.5 KB
    __shared__ __align__(16) float s_wf[2*ICC*16*12];    // 6.1 KB (stride-12 pad)

    const int b   = blockIdx.y;
    const int ocg = blockIdx.z;
    const int gy0 = blockIdx.x * 16;
    const int tid = threadIdx.x;
    const int tx  = tid & 31;
    const int y0  = (tid >> 5) * 2;
    const int NCH = CIN / ICC;

    const unsigned s_in_a = (unsigned)__cvta_generic_to_shared(s_in);
    const unsigned s_wf_a = (unsigned)__cvta_generic_to_shared(s_wf);

    unsigned long long acc[2][16];
#pragma unroll
    for (int r = 0; r < 2; r++)
#pragma unroll
        for (int o = 0; o < 16; o++) acc[r][o] = 0ull;

    const float* xb = x + (size_t)b * CIN * LPIX;
    const float* wb = w + (size_t)(ocg*16) * CIN * 9;

    // permanent-zero halo columns, both buffers (written once)
    for (int j = tid; j < 2*ICC*18; j += 256) {
        s_in[j*72 + 3]  = 0.f;
        s_in[j*72 + 68] = 0.f;
    }

    // stage chunk c0 into buffer buf (async; one commit group)
    auto stage = [&](int c0, int buf) {
        const int ibase = buf*ICC*1296;
        for (int j = tid; j < ICC*288; j += 256) {     // 288 = 18 rows * 16 q
            int ic  = j / 288;
            int rem = j - ic*288;
            int row = rem >> 4;
            int q   = rem & 15;
            int gy  = gy0 - 1 + row;
            int off = ibase + ic*1296 + row*72 + 4 + q*4;
            if ((unsigned)gy < 64u)
                cpasync16(s_in_a + off*4,
                          xb + (size_t)(c0 + ic)*LPIX + gy*64 + q*4);
            else
                *reinterpret_cast<float4*>(&s_in[off]) =
                    make_float4(0.f, 0.f, 0.f, 0.f);
        }
        for (int j = tid; j < ICC*144; j += 256) {
            int ic = j / 144;
            int r  = j - ic*144;
            int o  = r / 9;
            int k  = r - o*9;
            cpasync4(s_wf_a + (buf*ICC*192 + ic*192 + o*12 + k)*4,
                     wb + (size_t)o*CIN*9 + (c0 + ic)*9 + k);
        }
        asm volatile("cp.async.commit_group;" ::: "memory");
    };

    stage(0, 0);

    for (int c = 0; c < NCH; ++c) {
        if (c) __syncthreads();          // prev compute done before overwrite
        if (c + 1 < NCH) {
            stage((c + 1)*ICC, (c + 1) & 1);
            asm volatile("cp.async.wait_group 1;" ::: "memory");
        } else {
            asm volatile("cp.async.wait_group 0;" ::: "memory");
        }
        __syncthreads();

        const int buf = c & 1;
        for (int ic = 0; ic < ICC; ++ic) {
            const float* base = &s_in[buf*ICC*1296 + ic*1296 + y0*72 + 2*tx + 3];
            unsigned long long pr[4][3];
#pragma unroll
            for (int r = 0; r < 4; r++) {
                float f0 = base[r*72 + 0];
                float f1 = base[r*72 + 1];
                float f2 = base[r*72 + 2];
                float f3 = base[r*72 + 3];
                pr[r][0] = pk2(f0, f1);
                pr[r][1] = pk2(f1, f2);
                pr[r][2] = pk2(f2, f3);
            }
            const float* wp = &s_wf[buf*ICC*192 + ic*192];
#pragma unroll
            for (int o = 0; o < 16; o++) {
                // 9 taps via 2x LDS.128 + 1x LDS.32 (stride-12, 16B-aligned)
                float4 wA = *reinterpret_cast<const float4*>(wp + o*12);
                float4 wB = *reinterpret_cast<const float4*>(wp + o*12 + 4);
                float  w8 = wp[o*12 + 8];
                float wt[9] = { wA.x, wA.y, wA.z, wA.w,
                                wB.x, wB.y, wB.z, wB.w, w8 };
                unsigned long long pa = 0ull, pb = 0ull;
#pragma unroll
                for (int ky = 0; ky < 3; ky++)
#pragma unroll
                    for (int kx = 0; kx < 3; kx++) {
                        float wf = wt[ky*3 + kx];
                        unsigned long long wv = pk2(wf, wf);
                        pa = fma2(pr[ky    ][kx], wv, pa);
                        pb = fma2(pr[ky + 1][kx], wv, pb);
                    }
                acc[0][o] = add2(acc[0][o], pa);
                acc[1][o] = add2(acc[1][o], pb);
            }
        }
    }

    // epilogue: BN (inference) + ReLU, float2 stores
#pragma unroll
    for (int o = 0; o < 16; o++) {
        int   oc = ocg*16 + o;
        float sc = (float)((double)gg[oc] / sqrt((double)vv[oc] + 1e-5));
        float sh = bb[oc] - mm[oc] * sc;
#pragma unroll
        for (int rr = 0; rr < 2; rr++) {
            float lo, hi;
            unpk2(acc[rr][o], lo, hi);
            float v0 = fmaf(lo, sc, sh); v0 = v0 > 0.f ? v0 : 0.f;
            float v1 = fmaf(hi, sc, sh); v1 = v1 > 0.f ? v1 : 0.f;
            int gy = gy0 + y0 + rr;
            *reinterpret_cast<float2*>(
                &out[((size_t)(b*HID + oc))*LPIX + gy*64 + 2*tx]) =
                make_float2(v0, v1);
        }
    }
}

// ---------------------------------------------------------------------------
// 1x1 conv (HID->1) + bias -> g_l64. grid (16, NB), 256 thr
// ---------------------------------------------------------------------------
__global__ void __launch_bounds__(256)
conv1x1_bias(const float* __restrict__ h, const float* __restrict__ w3,
             const float* __restrict__ b3)
{
    __shared__ float sw[HID];
    const int b = blockIdx.y;
    const int p = blockIdx.x * 256 + threadIdx.x;
    if (threadIdx.x < HID) sw[threadIdx.x] = w3[threadIdx.x];
    __syncthreads();
    const float* hb = h + (size_t)b * HID * LPIX + p;
    float a = 0.f;
#pragma unroll 8
    for (int oc = 0; oc < HID; oc++) a = fmaf(sw[oc], hb[(size_t)oc * LPIX], a);
    g_l64[b * LPIX + p] = a + b3[0];
}

// ---------------------------------------------------------------------------
// bilinear 4x upsample (half-pixel, edge-clamp) + logits + sigmoid(double)
// ---------------------------------------------------------------------------
__global__ void __launch_bounds__(256)
upsample_sigmoid(float* __restrict__ outAll)
{
    const int idx = blockIdx.x * 256 + threadIdx.x;   // 0 .. NB*NPIX-1 exact
    const int b = idx >> 16;
    const int p = idx & 65535;
    const int oy = p >> 8, ox = p & 255;
    float sy = fmaf((float)oy, 0.25f, -0.375f);
    float sx = fmaf((float)ox, 0.25f, -0.375f);
    float fy = floorf(sy), fx = floorf(sx);
    float wy = sy - fy,    wx = sx - fx;
    int y0 = (int)fy, x0 = (int)fx;
    int y0c = y0 < 0 ? 0 : y0;
    int y1c = y0 + 1 > 63 ? 63 : y0 + 1;
    int x0c = x0 < 0 ? 0 : x0;
    int x1c = x0 + 1 > 63 ? 63 : x0 + 1;
    const float* L = g_l64 + b * LPIX;
    float v00 = L[y0c*64 + x0c], v01 = L[y0c*64 + x1c];
    float v10 = L[y1c*64 + x0c], v11 = L[y1c*64 + x1c];
    float a, c;
    if (y0c == y1c) { a = v00; c = v01; }
    else { a = fmaf(wy, v10, (1.0f - wy) * v00); c = fmaf(wy, v11, (1.0f - wy) * v01); }
    float lg = (x0c == x1c) ? a : fmaf(wx, c, (1.0f - wx) * a);
    outAll[OFF_LOG + idx] = lg;
    double hv = 1.0 / (1.0 + exp(-(double)lg));
    outAll[OFF_HEAT + idx] = (float)hv;
}

// ---------------------------------------------------------------------------
// horizontal 9-window max of heatmap -> g_rmax
// ---------------------------------------------------------------------------
__global__ void __launch_bounds__(256)
rowmax_k(const float* __restrict__ heat)
{
    const int idx = blockIdx.x * 256 + threadIdx.x;
    const int b = idx >> 16, p = idx & 65535;
    const int y = p >> 8,  x = p & 255;
    const float* H = heat + b * NPIX + y * 256;
    float m = -INFINITY;
#pragma unroll
    for (int dx = -4; dx <= 4; dx++) {
        int xx = x + dx;
        if ((unsigned)xx < 256u) m = fmaxf(m, H[xx]);
    }
    g_rmax[b * NPIX + p] = m;
}

// ---------------------------------------------------------------------------
// per-sample point extraction. grid NB, block 1024. thread t owns pixels
// [64t, 64t+64) (contiguous => rank-select order is global index order).
// ---------------------------------------------------------------------------
__global__ void __launch_bounds__(1024)
sample_k(const float* __restrict__ heat, float* __restrict__ outAll)
{
    __shared__ float stv[1024*3];
    __shared__ int   sti[1024*3];
    __shared__ float smv[1024];
    __shared__ int   smi[1024];
    __shared__ int   scnt[1024];
    __shared__ int   s_r[2], s_sel[2];

    const int b = blockIdx.x, t = threadIdx.x;
    const float* H = heat + b * NPIX;
    const float* R = g_rmax + b * NPIX;

    float t0v = -INFINITY, t1v = -INFINITY, t2v = -INFINITY;
    int   t0i = 0x7fffffff, t1i = 0x7fffffff, t2i = 0x7fffffff;
    float mv = -INFINITY; int mi = 0;
    int cnt = 0;
    const int base = t * 64;
    for (int k = 0; k < 64; k++) {
        int p = base + k, y = p >> 8, x = p & 255;
        float v = H[p];
        if (v > mv) { mv = v; mi = p; }
        if (v < 0.3f) cnt++;
        float lm = -INFINITY;
#pragma unroll
        for (int dy = -4; dy <= 4; dy++) {
            int yy = y + dy;
            if ((unsigned)yy < 256u) lm = fmaxf(lm, R[yy*256 + x]);
        }
        if (v == lm && v > 0.1f) {
            if (v > t0v)      { t2v=t1v; t2i=t1i; t1v=t0v; t1i=t0i; t0v=v; t0i=p; }
            else if (v > t1v) { t2v=t1v; t2i=t1i; t1v=v;   t1i=p; }
            else if (v > t2v) { t2v=v;   t2i=p; }
        }
    }
    stv[t*3] = t0v; stv[t*3+1] = t1v; stv[t*3+2] = t2v;
    sti[t*3] = t0i; sti[t*3+1] = t1i; sti[t*3+2] = t2i;
    smv[t] = mv; smi[t] = mi;
    scnt[t] = cnt;
    __syncthreads();

    // tree reduce: argmax (tie -> lower idx) + top-3 merge (val desc, tie -> lower idx)
    for (int s = 512; s > 0; s >>= 1) {
        if (t < s) {
            float ov = smv[t+s]; int oi = smi[t+s];
            if (ov > smv[t] || (ov == smv[t] && oi < smi[t])) { smv[t] = ov; smi[t] = oi; }
            float Av[3] = { stv[t*3], stv[t*3+1], stv[t*3+2] };
            int   Ai[3] = { sti[t*3], sti[t*3+1], sti[t*3+2] };
            float Bv[3] = { stv[(t+s)*3], stv[(t+s)*3+1], stv[(t+s)*3+2] };
            int   Bi[3] = { sti[(t+s)*3], sti[(t+s)*3+1], sti[(t+s)*3+2] };
            int ia = 0, ib = 0;
#pragma unroll
            for (int k = 0; k < 3; k++) {
                bool ta = (Av[ia] > Bv[ib]) || (Av[ia] == Bv[ib] && Ai[ia] < Bi[ib]);
                if (ta) { stv[t*3+k] = Av[ia]; sti[t*3+k] = Ai[ia]; ia++; }
                else    { stv[t*3+k] = Bv[ib]; sti[t*3+k] = Bi[ib]; ib++; }
            }
        }
        __syncthreads();
    }

    // inclusive scan of counts (<0.3)
    int myc = cnt;
    for (int off = 1; off < 1024; off <<= 1) {
        int add = (t >= off) ? scnt[t - off] : 0;
        __syncthreads();
        scnt[t] += add;
        __syncthreads();
    }
    int n = scnt[1023];
    int prefEx = scnt[t] - myc;
    float thr = 0.3f;
    float maxval = smv[0];
    __syncthreads();

    if (n == 0) {  // fallback mask: smap < max(smap)  (uniform branch)
        thr = maxval;
        myc = 0;
        for (int k = 0; k < 64; k++) if (H[base + k] < thr) myc++;
        scnt[t] = myc;
        __syncthreads();
        for (int off = 1; off < 1024; off <<= 1) {
            int add = (t >= off) ? scnt[t - off] : 0;
            __syncthreads();
            scnt[t] += add;
            __syncthreads();
        }
        n = scnt[1023];
        prefEx = scnt[t] - myc;
        __syncthreads();
    }

    if (t == 0) {
        // JAX threefry, partitionable mode:
        // split: key_b = threefry((0,42),(0,b)) with both lanes stacked
        unsigned k0, k1;
        tf2x32(0u, 42u, 0u, (unsigned)b, k0, k1);
        // random_bits: counter j encrypts (0,j); bits_j = o0 ^ o1
        float nf  = (float)(n > 0 ? n : 1);
        int   nm1 = (n - 1 > 0) ? n - 1 : 0;
#pragma unroll
        for (int j = 0; j < 2; j++) {
            unsigned a0, a1;
            tf2x32(k0, k1, 0u, (unsigned)j, a0, a1);
            unsigned bits = a0 ^ a1;
            float u = __uint_as_float((bits >> 9) | 0x3f800000u) - 1.0f;
            int r = (int)(u * nf);
            if (r > nm1) r = nm1;
            s_r[j] = r;
        }
        s_sel[0] = -1; s_sel[1] = -1;
    }
    __syncthreads();

    if (n > 0) {
        for (int j = 0; j < 2; j++) {
            int r = s_r[j];
            if (r >= prefEx && r < prefEx + myc) {
                int need = r - prefEx;
                for (int k = 0; k < 64; k++) {
                    if (H[base + k] < thr) {
                        if (need == 0) { s_sel[j] = base + k; break; }
                        need--;
                    }
                }
            }
        }
    }
    __syncthreads();

    if (t == 0) {
        float* oc = outAll + OFF_COORD + b * 10;
        float* ol = outAll + OFF_LAB   + b * 5;
#pragma unroll
        for (int i = 0; i < 3; i++) {
            bool valid = stv[i] > -INFINITY;
            float xx = valid ? (float)(sti[i] & 255) : 0.f;
            float yy = valid ? (float)(sti[i] >> 8)  : 0.f;
            float lb = valid ? 1.f : -1.f;
            if (i == 0) {
                if (!valid) { xx = (float)(smi[0] & 255); yy = (float)(smi[0] >> 8); }
                lb = 1.f;
            }
            oc[2*i] = xx; oc[2*i + 1] = yy; ol[i] = lb;
        }
#pragma unroll
        for (int j = 0; j < 2; j++) {
            int s = s_sel[j];
            oc[6 + 2*j] = (s >= 0) ? (float)(s & 255) : 0.f;
            oc[7 + 2*j] = (s >= 0) ? (float)(s >> 8)  : 0.f;
            ol[3 + j] = 0.f;
        }
    }
}

// ---------------------------------------------------------------------------
extern "C" void kernel_launch(void* const* d_in, const int* in_sizes, int n_in,
                              void* d_out, int out_size)
{
    const float* x  = (const float*)d_in[0];
    const float* w1 = (const float*)d_in[1];
    const float* g1 = (const float*)d_in[2];
    const float* b1 = (const float*)d_in[3];
    const float* m1 = (const float*)d_in[4];
    const float* v1 = (const float*)d_in[5];
    const float* w2 = (const float*)d_in[6];
    const float* g2 = (const float*)d_in[7];
    const float* b2 = (const float*)d_in[8];
    const float* m2 = (const float*)d_in[9];
    const float* v2 = (const float*)d_in[10];
    const float* w3 = (const float*)d_in[11];
    const float* b3 = (const float*)d_in[12];
    float* out = (float*)d_out;

    void* p1; cudaGetSymbolAddress(&p1, g_h1);
    void* p2; cudaGetSymbolAddress(&p2, g_h2);
    float* h1 = (float*)p1;
    float* h2 = (float*)p2;

    // 3 dummy launches keep ncu's fixed profiling slot on conv3x3_bn_relu<256>.
    dummy_k<<<1, 32>>>();
    dummy_k<<<1, 32>>>();
    dummy_k<<<1, 32>>>();

    dim3 cgrid(4, NB, HID / 16);
    conv3x3_bn_relu<256><<<cgrid, 256>>>(x,  w1, g1, b1, m1, v1, h1);
    conv3x3_bn_relu<64> <<<cgrid, 256>>>(h1, w2, g2, b2, m2, v2, h2);
    conv1x1_bias<<<dim3(LPIX / 256, NB), 256>>>(h2, w3, b3);

    const int nblk = (NB * NPIX) / 256;          // 8192, exact
    upsample_sigmoid<<<nblk, 256>>>(out);
    rowmax_k<<<nblk, 256>>>(out + OFF_HEAT);
    sample_k<<<NB, 1024>>>(out + OFF_HEAT, out);
}

// round 17
// speedup vs baseline: 1.0968x; 1.0968x over previous
#include <cuda_runtime.h>
#include <math.h>

#define NB   32
#define HID  64
#define LHW  64
#define LPIX (LHW*LHW)       // 4096
#define OHW  256
#define NPIX (OHW*OHW)       // 65536

#define OFF_HEAT  0
#define N_HEAT    (NB*NPIX)              // 2097152
#define OFF_COORD (N_HEAT)
#define OFF_LAB   (OFF_COORD + NB*10)    // 2097472
#define OFF_LOG   (OFF_LAB + NB*5)       // 2097632

// scratch (device globals: allocation-free)
__device__ __align__(16) float g_h1[NB*HID*LPIX];
__device__ __align__(16) float g_h2[NB*HID*LPIX];
__device__ __align__(16) float g_l64[NB*LPIX];
__device__ __align__(16) float g_rmax[NB*NPIX];

// ---------------------------------------------------------------------------
// f32x2 packed helpers (sm_103a FFMA2 path — per-lane IEEE fp32, bit-exact)
// ---------------------------------------------------------------------------
__device__ __forceinline__ unsigned long long pk2(float lo, float hi) {
    unsigned long long r;
    asm("mov.b64 %0, {%1, %2};" : "=l"(r) : "f"(lo), "f"(hi));
    return r;
}
__device__ __forceinline__ unsigned long long fma2(unsigned long long a,
                                                   unsigned long long b,
                                                   unsigned long long c) {
    unsigned long long d;
    asm("fma.rn.f32x2 %0, %1, %2, %3;" : "=l"(d) : "l"(a), "l"(b), "l"(c));
    return d;
}
__device__ __forceinline__ unsigned long long add2(unsigned long long a,
                                                   unsigned long long b) {
    unsigned long long d;
    asm("add.rn.f32x2 %0, %1, %2;" : "=l"(d) : "l"(a), "l"(b));
    return d;
}
__device__ __forceinline__ void unpk2(unsigned long long v, float &lo, float &hi) {
    asm("mov.b64 {%0, %1}, %2;" : "=f"(lo), "=f"(hi) : "l"(v));
}
__device__ __forceinline__ void cpasync16(unsigned dst, const void* src) {
    asm volatile("cp.async.ca.shared.global [%0], [%1], 16;"
                 :: "r"(dst), "l"(src) : "memory");
}
__device__ __forceinline__ void cpasync4(unsigned dst, const void* src) {
    asm volatile("cp.async.ca.shared.global [%0], [%1], 4;"
                 :: "r"(dst), "l"(src) : "memory");
}

// ---------------------------------------------------------------------------
// threefry2x32 (JAX-compatible, 20 rounds)
// ---------------------------------------------------------------------------
__device__ __forceinline__ void tf2x32(unsigned k0, unsigned k1,
                                       unsigned x0, unsigned x1,
                                       unsigned &o0, unsigned &o1)
{
    unsigned ks0 = k0, ks1 = k1, ks2 = k0 ^ k1 ^ 0x1BD11BDAu;
    x0 += ks0; x1 += ks1;
#define TFR(r) { x0 += x1; x1 = (x1 << (r)) | (x1 >> (32 - (r))); x1 ^= x0; }
    TFR(13) TFR(15) TFR(26) TFR(6)   x0 += ks1; x1 += ks2 + 1u;
    TFR(17) TFR(29) TFR(16) TFR(24)  x0 += ks2; x1 += ks0 + 2u;
    TFR(13) TFR(15) TFR(26) TFR(6)   x0 += ks0; x1 += ks1 + 3u;
    TFR(17) TFR(29) TFR(16) TFR(24)  x0 += ks1; x1 += ks2 + 4u;
    TFR(13) TFR(15) TFR(26) TFR(6)   x0 += ks2; x1 += ks0 + 5u;
#undef TFR
    o0 = x0; o1 = x1;
}

// ---------------------------------------------------------------------------
// dummy kernels: keep ncu's fixed profiling slot on conv3x3 (3 launches)
// ---------------------------------------------------------------------------
__global__ void dummy_k() {}

// ---------------------------------------------------------------------------
// conv3x3 (pad1) + inference BN + ReLU, f32x2-packed, cp.async double-buffered.
// Tile: full-width 64 x 16 rows, 8 oc per block; ICC=4 per chunk, 2 buffers.
// block 256 thr: tx=tid&31 -> x-pair 2tx; y0=(tid>>5)*2 -> rows y0, y0+1.
// grid (4 strips, NB, HID/8); 2 rows x 2 px x 8 oc per thread.
// 8 oc halves accumulator regs -> target 3 blocks/SM (6 warps/SMSP).
// smem rows stride 72: image col x at smem col x+4; cols 3 / 68 permanent 0.
// R16 fix: weight staging is a grid-stride loop (ICC*72=288 > 256 threads;
// R15's `if (tid < 288)` left 32 weights unstaged -> garbage heatmap).
// ---------------------------------------------------------------------------
#define ICC 4
template<int CIN>
__global__ void __launch_bounds__(256, 3)
conv3x3_bn_relu(const float* __restrict__ x,  const float* __restrict__ w,
                const float* __restrict__ gg, const float* __restrict__ bb,
                const float* __restrict__ mm, const float* __restrict__ vv,
                float* __restrict__ out)
{
    __shared__ __align__(16) float s_in[2*ICC*18*72];    // 41.5 KB
    __shared__ float               s_wf[2*ICC*72];       // 2.3 KB

    const int b   = blockIdx.y;
    const int ocg = blockIdx.z;          // 0..7, 8 oc each
    const int gy0 = blockIdx.x * 16;
    const int tid = threadIdx.x;
    const int tx  = tid & 31;
    const int y0  = (tid >> 5) * 2;
    const int NCH = CIN / ICC;

    const unsigned s_in_a = (unsigned)__cvta_generic_to_shared(s_in);
    const unsigned s_wf_a = (unsigned)__cvta_generic_to_shared(s_wf);

    unsigned long long acc[2][8];
#pragma unroll
    for (int r = 0; r < 2; r++)
#pragma unroll
        for (int o = 0; o < 8; o++) acc[r][o] = 0ull;

    const float* xb = x + (size_t)b * CIN * LPIX;
    const float* wb = w + (size_t)(ocg*8) * CIN * 9;

    // permanent-zero halo columns, both buffers (written once)
    for (int j = tid; j < 2*ICC*18; j += 256) {
        s_in[j*72 + 3]  = 0.f;
        s_in[j*72 + 68] = 0.f;
    }

    // stage chunk c0 into buffer buf (async; one commit group)
    auto stage = [&](int c0, int buf) {
        const int ibase = buf*ICC*1296;
        for (int j = tid; j < ICC*288; j += 256) {     // 288 = 18 rows * 16 q
            int ic  = j / 288;
            int rem = j - ic*288;
            int row = rem >> 4;
            int q   = rem & 15;
            int gy  = gy0 - 1 + row;
            int off = ibase + ic*1296 + row*72 + 4 + q*4;
            if ((unsigned)gy < 64u)
                cpasync16(s_in_a + off*4,
                          xb + (size_t)(c0 + ic)*LPIX + gy*64 + q*4);
            else
                *reinterpret_cast<float4*>(&s_in[off]) =
                    make_float4(0.f, 0.f, 0.f, 0.f);
        }
        for (int j = tid; j < ICC*72; j += 256) {      // 288 weights (fix!)
            int ic = j / 72;
            int r  = j - ic*72;
            int o  = r / 9;
            int k  = r - o*9;
            cpasync4(s_wf_a + (buf*ICC*72 + j)*4,
                     wb + (size_t)o*CIN*9 + (c0 + ic)*9 + k);
        }
        asm volatile("cp.async.commit_group;" ::: "memory");
    };

    stage(0, 0);

    for (int c = 0; c < NCH; ++c) {
        if (c) __syncthreads();          // prev compute done before overwrite
        if (c + 1 < NCH) {
            stage((c + 1)*ICC, (c + 1) & 1);
            asm volatile("cp.async.wait_group 1;" ::: "memory");
        } else {
            asm volatile("cp.async.wait_group 0;" ::: "memory");
        }
        __syncthreads();

        const int buf = c & 1;
        for (int ic = 0; ic < ICC; ++ic) {
            const float* base = &s_in[buf*ICC*1296 + ic*1296 + y0*72 + 2*tx + 3];
            unsigned long long pr[4][3];
#pragma unroll
            for (int r = 0; r < 4; r++) {
                float f0 = base[r*72 + 0];
                float f1 = base[r*72 + 1];
                float f2 = base[r*72 + 2];
                float f3 = base[r*72 + 3];
                pr[r][0] = pk2(f0, f1);
                pr[r][1] = pk2(f1, f2);
                pr[r][2] = pk2(f2, f3);
            }
            const float* wp = &s_wf[buf*ICC*72 + ic*72];
#pragma unroll
            for (int o = 0; o < 8; o++) {
                unsigned long long pa = 0ull, pb = 0ull;
#pragma unroll
                for (int ky = 0; ky < 3; ky++)
#pragma unroll
                    for (int kx = 0; kx < 3; kx++) {
                        float wf = wp[o*9 + ky*3 + kx];
                        unsigned long long wv = pk2(wf, wf);
                        pa = fma2(pr[ky    ][kx], wv, pa);
                        pb = fma2(pr[ky + 1][kx], wv, pb);
                    }
                acc[0][o] = add2(acc[0][o], pa);
                acc[1][o] = add2(acc[1][o], pb);
            }
        }
    }

    // epilogue: BN (inference) + ReLU, float2 stores
#pragma unroll
    for (int o = 0; o < 8; o++) {
        int   oc = ocg*8 + o;
        float sc = (float)((double)gg[oc] / sqrt((double)vv[oc] + 1e-5));
        float sh = bb[oc] - mm[oc] * sc;
#pragma unroll
        for (int rr = 0; rr < 2; rr++) {
            float lo, hi;
            unpk2(acc[rr][o], lo, hi);
            float v0 = fmaf(lo, sc, sh); v0 = v0 > 0.f ? v0 : 0.f;
            float v1 = fmaf(hi, sc, sh); v1 = v1 > 0.f ? v1 : 0.f;
            int gy = gy0 + y0 + rr;
            *reinterpret_cast<float2*>(
                &out[((size_t)(b*HID + oc))*LPIX + gy*64 + 2*tx]) =
                make_float2(v0, v1);
        }
    }
}

// ---------------------------------------------------------------------------
// 1x1 conv (HID->1) + bias -> g_l64. grid (16, NB), 256 thr
// ---------------------------------------------------------------------------
__global__ void __launch_bounds__(256)
conv1x1_bias(const float* __restrict__ h, const float* __restrict__ w3,
             const float* __restrict__ b3)
{
    __shared__ float sw[HID];
    const int b = blockIdx.y;
    const int p = blockIdx.x * 256 + threadIdx.x;
    if (threadIdx.x < HID) sw[threadIdx.x] = w3[threadIdx.x];
    __syncthreads();
    const float* hb = h + (size_t)b * HID * LPIX + p;
    float a = 0.f;
#pragma unroll 8
    for (int oc = 0; oc < HID; oc++) a = fmaf(sw[oc], hb[(size_t)oc * LPIX], a);
    g_l64[b * LPIX + p] = a + b3[0];
}

// ---------------------------------------------------------------------------
// bilinear 4x upsample (half-pixel, edge-clamp) + logits + sigmoid(double)
// ---------------------------------------------------------------------------
__global__ void __launch_bounds__(256)
upsample_sigmoid(float* __restrict__ outAll)
{
    const int idx = blockIdx.x * 256 + threadIdx.x;   // 0 .. NB*NPIX-1 exact
    const int b = idx >> 16;
    const int p = idx & 65535;
    const int oy = p >> 8, ox = p & 255;
    float sy = fmaf((float)oy, 0.25f, -0.375f);
    float sx = fmaf((float)ox, 0.25f, -0.375f);
    float fy = floorf(sy), fx = floorf(sx);
    float wy = sy - fy,    wx = sx - fx;
    int y0 = (int)fy, x0 = (int)fx;
    int y0c = y0 < 0 ? 0 : y0;
    int y1c = y0 + 1 > 63 ? 63 : y0 + 1;
    int x0c = x0 < 0 ? 0 : x0;
    int x1c = x0 + 1 > 63 ? 63 : x0 + 1;
    const float* L = g_l64 + b * LPIX;
    float v00 = L[y0c*64 + x0c], v01 = L[y0c*64 + x1c];
    float v10 = L[y1c*64 + x0c], v11 = L[y1c*64 + x1c];
    float a, c;
    if (y0c == y1c) { a = v00; c = v01; }
    else { a = fmaf(wy, v10, (1.0f - wy) * v00); c = fmaf(wy, v11, (1.0f - wy) * v01); }
    float lg = (x0c == x1c) ? a : fmaf(wx, c, (1.0f - wx) * a);
    outAll[OFF_LOG + idx] = lg;
    double hv = 1.0 / (1.0 + exp(-(double)lg));
    outAll[OFF_HEAT + idx] = (float)hv;
}

// ---------------------------------------------------------------------------
// horizontal 9-window max of heatmap -> g_rmax
// ---------------------------------------------------------------------------
__global__ void __launch_bounds__(256)
rowmax_k(const float* __restrict__ heat)
{
    const int idx = blockIdx.x * 256 + threadIdx.x;
    const int b = idx >> 16, p = idx & 65535;
    const int y = p >> 8,  x = p & 255;
    const float* H = heat + b * NPIX + y * 256;
    float m = -INFINITY;
#pragma unroll
    for (int dx = -4; dx <= 4; dx++) {
        int xx = x + dx;
        if ((unsigned)xx < 256u) m = fmaxf(m, H[xx]);
    }
    g_rmax[b * NPIX + p] = m;
}

// ---------------------------------------------------------------------------
// per-sample point extraction. grid NB, block 1024. thread t owns pixels
// [64t, 64t+64) (contiguous => rank-select order is global index order).
// ---------------------------------------------------------------------------
__global__ void __launch_bounds__(1024)
sample_k(const float* __restrict__ heat, float* __restrict__ outAll)
{
    __shared__ float stv[1024*3];
    __shared__ int   sti[1024*3];
    __shared__ float smv[1024];
    __shared__ int   smi[1024];
    __shared__ int   scnt[1024];
    __shared__ int   s_r[2], s_sel[2];

    const int b = blockIdx.x, t = threadIdx.x;
    const float* H = heat + b * NPIX;
    const float* R = g_rmax + b * NPIX;

    float t0v = -INFINITY, t1v = -INFINITY, t2v = -INFINITY;
    int   t0i = 0x7fffffff, t1i = 0x7fffffff, t2i = 0x7fffffff;
    float mv = -INFINITY; int mi = 0;
    int cnt = 0;
    const int base = t * 64;
    for (int k = 0; k < 64; k++) {
        int p = base + k, y = p >> 8, x = p & 255;
        float v = H[p];
        if (v > mv) { mv = v; mi = p; }
        if (v < 0.3f) cnt++;
        float lm = -INFINITY;
#pragma unroll
        for (int dy = -4; dy <= 4; dy++) {
            int yy = y + dy;
            if ((unsigned)yy < 256u) lm = fmaxf(lm, R[yy*256 + x]);
        }
        if (v == lm && v > 0.1f) {
            if (v > t0v)      { t2v=t1v; t2i=t1i; t1v=t0v; t1i=t0i; t0v=v; t0i=p; }
            else if (v > t1v) { t2v=t1v; t2i=t1i; t1v=v;   t1i=p; }
            else if (v > t2v) { t2v=v;   t2i=p; }
        }
    }
    stv[t*3] = t0v; stv[t*3+1] = t1v; stv[t*3+2] = t2v;
    sti[t*3] = t0i; sti[t*3+1] = t1i; sti[t*3+2] = t2i;
    smv[t] = mv; smi[t] = mi;
    scnt[t] = cnt;
    __syncthreads();

    // tree reduce: argmax (tie -> lower idx) + top-3 merge (val desc, tie -> lower idx)
    for (int s = 512; s > 0; s >>= 1) {
        if (t < s) {
            float ov = smv[t+s]; int oi = smi[t+s];
            if (ov > smv[t] || (ov == smv[t] && oi < smi[t])) { smv[t] = ov; smi[t] = oi; }
            float Av[3] = { stv[t*3], stv[t*3+1], stv[t*3+2] };
            int   Ai[3] = { sti[t*3], sti[t*3+1], sti[t*3+2] };
            float Bv[3] = { stv[(t+s)*3], stv[(t+s)*3+1], stv[(t+s)*3+2] };
            int   Bi[3] = { sti[(t+s)*3], sti[(t+s)*3+1], sti[(t+s)*3+2] };
            int ia = 0, ib = 0;
#pragma unroll
            for (int k = 0; k < 3; k++) {
                bool ta = (Av[ia] > Bv[ib]) || (Av[ia] == Bv[ib] && Ai[ia] < Bi[ib]);
                if (ta) { stv[t*3+k] = Av[ia]; sti[t*3+k] = Ai[ia]; ia++; }
                else    { stv[t*3+k] = Bv[ib]; sti[t*3+k] = Bi[ib]; ib++; }
            }
        }
        __syncthreads();
    }

    // inclusive scan of counts (<0.3)
    int myc = cnt;
    for (int off = 1; off < 1024; off <<= 1) {
        int add = (t >= off) ? scnt[t - off] : 0;
        __syncthreads();
        scnt[t] += add;
        __syncthreads();
    }
    int n = scnt[1023];
    int prefEx = scnt[t] - myc;
    float thr = 0.3f;
    float maxval = smv[0];
    __syncthreads();

    if (n == 0) {  // fallback mask: smap < max(smap)  (uniform branch)
        thr = maxval;
        myc = 0;
        for (int k = 0; k < 64; k++) if (H[base + k] < thr) myc++;
        scnt[t] = myc;
        __syncthreads();
        for (int off = 1; off < 1024; off <<= 1) {
            int add = (t >= off) ? scnt[t - off] : 0;
            __syncthreads();
            scnt[t] += add;
            __syncthreads();
        }
        n = scnt[1023];
        prefEx = scnt[t] - myc;
        __syncthreads();
    }

    if (t == 0) {
        // JAX threefry, partitionable mode:
        // split: key_b = threefry((0,42),(0,b)) with both lanes stacked
        unsigned k0, k1;
        tf2x32(0u, 42u, 0u, (unsigned)b, k0, k1);
        // random_bits: counter j encrypts (0,j); bits_j = o0 ^ o1
        float nf  = (float)(n > 0 ? n : 1);
        int   nm1 = (n - 1 > 0) ? n - 1 : 0;
#pragma unroll
        for (int j = 0; j < 2; j++) {
            unsigned a0, a1;
            tf2x32(k0, k1, 0u, (unsigned)j, a0, a1);
            unsigned bits = a0 ^ a1;
            float u = __uint_as_float((bits >> 9) | 0x3f800000u) - 1.0f;
            int r = (int)(u * nf);
            if (r > nm1) r = nm1;
            s_r[j] = r;
        }
        s_sel[0] = -1; s_sel[1] = -1;
    }
    __syncthreads();

    if (n > 0) {
        for (int j = 0; j < 2; j++) {
            int r = s_r[j];
            if (r >= prefEx && r < prefEx + myc) {
                int need = r - prefEx;
                for (int k = 0; k < 64; k++) {
                    if (H[base + k] < thr) {
                        if (need == 0) { s_sel[j] = base + k; break; }
                        need--;
                    }
                }
            }
        }
    }
    __syncthreads();

    if (t == 0) {
        float* oc = outAll + OFF_COORD + b * 10;
        float* ol = outAll + OFF_LAB   + b * 5;
#pragma unroll
        for (int i = 0; i < 3; i++) {
            bool valid = stv[i] > -INFINITY;
            float xx = valid ? (float)(sti[i] & 255) : 0.f;
            float yy = valid ? (float)(sti[i] >> 8)  : 0.f;
            float lb = valid ? 1.f : -1.f;
            if (i == 0) {
                if (!valid) { xx = (float)(smi[0] & 255); yy = (float)(smi[0] >> 8); }
                lb = 1.f;
            }
            oc[2*i] = xx; oc[2*i + 1] = yy; ol[i] = lb;
        }
#pragma unroll
        for (int j = 0; j < 2; j++) {
            int s = s_sel[j];
            oc[6 + 2*j] = (s >= 0) ? (float)(s & 255) : 0.f;
            oc[7 + 2*j] = (s >= 0) ? (float)(s >> 8)  : 0.f;
            ol[3 + j] = 0.f;
        }
    }
}

// ---------------------------------------------------------------------------
extern "C" void kernel_launch(void* const* d_in, const int* in_sizes, int n_in,
                              void* d_out, int out_size)
{
    const float* x  = (const float*)d_in[0];
    const float* w1 = (const float*)d_in[1];
    const float* g1 = (const float*)d_in[2];
    const float* b1 = (const float*)d_in[3];
    const float* m1 = (const float*)d_in[4];
    const float* v1 = (const float*)d_in[5];
    const float* w2 = (const float*)d_in[6];
    const float* g2 = (const float*)d_in[7];
    const float* b2 = (const float*)d_in[8];
    const float* m2 = (const float*)d_in[9];
    const float* v2 = (const float*)d_in[10];
    const float* w3 = (const float*)d_in[11];
    const float* b3 = (const float*)d_in[12];
    float* out = (float*)d_out;

    void* p1; cudaGetSymbolAddress(&p1, g_h1);
    void* p2; cudaGetSymbolAddress(&p2, g_h2);
    float* h1 = (float*)p1;
    float* h2 = (float*)p2;

    // 3 dummy launches keep ncu's fixed profiling slot on conv3x3_bn_relu<256>.
    dummy_k<<<1, 32>>>();
    dummy_k<<<1, 32>>>();
    dummy_k<<<1, 32>>>();

    dim3 cgrid(4, NB, HID / 8);
    conv3x3_bn_relu<256><<<cgrid, 256>>>(x,  w1, g1, b1, m1, v1, h1);
    conv3x3_bn_relu<64> <<<cgrid, 256>>>(h1, w2, g2, b2, m2, v2, h2);
    conv1x1_bias<<<dim3(LPIX / 256, NB), 256>>>(h2, w3, b3);

    const int nblk = (NB * NPIX) / 256;          // 8192, exact
    upsample_sigmoid<<<nblk, 256>>>(out);
    rowmax_k<<<nblk, 256>>>(out + OFF_HEAT);
    sample_k<<<NB, 1024>>>(out + OFF_HEAT, out);
}